// round 6
// baseline (speedup 1.0000x reference)
#include <cuda_runtime.h>

#define ROWS 1024
#define COLS 1024
#define NN (ROWS * COLS)

#define RHOGW 9810.0f            // RHO_W * GRAV
#define INV_SEC_PER_A (1.0f / 31556926.0f)
#define FLOW_COEFF 0.0405f

#define TS 32                    // output tile
#define KF 8                     // fused iterations per launch
#define RW (TS + 2*KF)           // 48
#define RN (RW * RW)             // 2304
#define SPAD RW                  // sq guard pad (one row each side)
#define PH 52                    // phi tile (region + halo 2)
#define GH 50                    // gs tile (region + halo 1)

#define NEG_INF __int_as_float(0xff800000)

// Scratch (device globals: no allocations allowed)
__device__ float g_phi[NN];
__device__ float g_runoff[NN];
__device__ float g_q[2][NN];

// ---------------- prep: phi + runoff, elementwise float4 ----------------
__global__ __launch_bounds__(256) void k_prep(const float* __restrict__ melt,
                                              const float* __restrict__ bed,
                                              const float* __restrict__ wp,
                                              const float* __restrict__ area) {
    int i = (blockIdx.x * blockDim.x + threadIdx.x) * 4;
    if (i >= NN) return;
    float4 b = *(const float4*)&bed[i];
    float4 w = *(const float4*)&wp[i];
    float4 m = *(const float4*)&melt[i];
    float4 a = *(const float4*)&area[i];
    float4 p, r;
    p.x = fmaf(RHOGW, b.x, w.x); p.y = fmaf(RHOGW, b.y, w.y);
    p.z = fmaf(RHOGW, b.z, w.z); p.w = fmaf(RHOGW, b.w, w.w);
    r.x = m.x * a.x * INV_SEC_PER_A; r.y = m.y * a.y * INV_SEC_PER_A;
    r.z = m.z * a.z * INV_SEC_PER_A; r.w = m.w * a.w * INV_SEC_PER_A;
    *(float4*)&g_phi[i] = p;
    *(float4*)&g_runoff[i] = r;
}

// ---------------- fused Jacobi: weights derived in-block from phi ----------------
// 256 threads (16x16), each owns a 3x3 patch of a 48x48 region (32x32 tile,
// halo 8). Stage A: phi tile (52x52, sentinel -INF) + gs tile (50x50) in smem,
// per-thread weights into registers. Stage B (same smem, aliased): q ping-pong,
// ring exchange, 8 iterations.
template <bool INIT, bool FINAL>
__global__ __launch_bounds__(256, 3)
void k_fused(int qsel,
             const float* __restrict__ conduit,
             float* __restrict__ out) {
    __shared__ __align__(16) float smem_raw[PH * PH + GH * GH];  // 5204 floats
    float* sphi = smem_raw;                    // PH*PH = 2704
    float* sgs  = smem_raw + PH * PH;          // GH*GH = 2500
    float (*sq)[RN + 2 * SPAD] = (float (*)[RN + 2 * SPAD])smem_raw;  // 2*2400 = 4800

    const int tid = threadIdx.x;
    const int tx = tid & 15, ty = tid >> 4;
    const int px = tx * 3, py = ty * 3;
    const int ox = blockIdx.x * TS - KF;
    const int oy = blockIdx.y * TS - KF;

    const float* __restrict__ qsrc = g_q[qsel];
    float*       __restrict__ qdst = g_q[qsel ^ 1];

    // ---- Stage A1: phi tile (global -> smem), -INF sentinel off-grid ----
    for (int idx = tid; idx < PH * PH; idx += 256) {
        int iy = idx / PH, ix = idx - iy * PH;
        int gy = oy + iy - 2, gx = ox + ix - 2;
        float p = NEG_INF;
        if (gx >= 0 && gx < COLS && gy >= 0 && gy < ROWS)
            p = g_phi[gy * COLS + gx];
        sphi[idx] = p;
    }
    __syncthreads();

    // ---- Stage A2: gs tile ----
    for (int idx = tid; idx < GH * GH; idx += 256) {
        int iy = idx / GH, ix = idx - iy * GH;
        int gy = oy + iy - 1, gx = ox + ix - 1;
        int c = (iy + 1) * PH + (ix + 1);
        float p = sphi[c];
        float s = 0.0f;
        s += fmaxf(p - sphi[c - 1], 0.0f);
        s += fmaxf(p - sphi[c + 1], 0.0f);
        s += fmaxf(p - sphi[c - PH], 0.0f);
        s += fmaxf(p - sphi[c + PH], 0.0f);
        // interior <=> core node (perimeter-only boundary status)
        bool interior = (gx >= 1) & (gx <= COLS - 2) & (gy >= 1) & (gy <= ROWS - 2);
        sgs[idx] = interior ? ((s > 0.0f) ? (1.0f / s) : 1.0f) : 0.0f;
    }
    __syncthreads();

    // ---- Stage A3: per-thread incoming weights + runoff + q0 into registers ----
    float4 w[3][3];
    float  ro[3][3];
    float  q[3][3];
#pragma unroll
    for (int r = 0; r < 3; r++) {
#pragma unroll
        for (int c = 0; c < 3; c++) {
            const int gy = oy + py + r, gx = ox + px + c;
            const bool ok = (gx >= 0) & (gx < COLS) & (gy >= 0) & (gy < ROWS);
            float4 wv = make_float4(0.0f, 0.0f, 0.0f, 0.0f);
            float rv = 0.0f, qv = 0.0f;
            if (ok) {
                const int pi = (py + r + 2) * PH + (px + c + 2);
                const int gi = (py + r + 1) * GH + (px + c + 1);
                const float p = sphi[pi];
                wv.x = fmaxf(sphi[pi - 1]  - p, 0.0f) * sgs[gi - 1];
                wv.y = fmaxf(sphi[pi + 1]  - p, 0.0f) * sgs[gi + 1];
                wv.z = fmaxf(sphi[pi - PH] - p, 0.0f) * sgs[gi - GH];
                wv.w = fmaxf(sphi[pi + PH] - p, 0.0f) * sgs[gi + GH];
                const int g = gy * COLS + gx;
                rv = g_runoff[g];
                qv = INIT ? rv : qsrc[g];
            }
            w[r][c] = wv; ro[r][c] = rv; q[r][c] = qv;
        }
    }
    __syncthreads();   // all phi/gs reads done before sq overwrites the smem

    // ---- Stage B: seed sq (guard pads + patch borders) ----
    if (tid < SPAD) {
        sq[0][tid] = 0.0f;
        sq[1][tid] = 0.0f;
        sq[0][SPAD + RN + tid] = 0.0f;
        sq[1][SPAD + RN + tid] = 0.0f;
    }
    const int base = SPAD + py * RW + px;
#pragma unroll
    for (int r = 0; r < 3; r++)
#pragma unroll
        for (int c = 0; c < 3; c++)
            if (!(r == 1 && c == 1)) sq[0][base + r * RW + c] = q[r][c];
    __syncthreads();

#pragma unroll
    for (int it = 0; it < KF; it++) {
        const int cur = it & 1;
        const float* __restrict__ qs = sq[cur];
        float*       __restrict__ qd = sq[cur ^ 1];

        // 12-ring from neighboring threads (previous iteration values)
        float t0 = qs[base - RW],     t1 = qs[base - RW + 1],     t2 = qs[base - RW + 2];
        float b0 = qs[base + 3 * RW], b1 = qs[base + 3 * RW + 1], b2 = qs[base + 3 * RW + 2];
        float l0 = qs[base - 1],      l1 = qs[base + RW - 1],     l2 = qs[base + 2 * RW - 1];
        float r0 = qs[base + 3],      r1 = qs[base + RW + 3],     r2 = qs[base + 2 * RW + 3];

        float n[3][3];
#pragma unroll
        for (int r = 0; r < 3; r++) {
#pragma unroll
            for (int c = 0; c < 3; c++) {
                const float lf = (c == 0) ? ((r == 0) ? l0 : (r == 1) ? l1 : l2) : q[r][c - 1];
                const float rt = (c == 2) ? ((r == 0) ? r0 : (r == 1) ? r1 : r2) : q[r][c + 1];
                const float up = (r == 0) ? ((c == 0) ? t0 : (c == 1) ? t1 : t2) : q[r - 1][c];
                const float dn = (r == 2) ? ((c == 0) ? b0 : (c == 1) ? b1 : b2) : q[r + 1][c];
                float acc = ro[r][c];
                acc = fmaf(w[r][c].x, lf, acc);
                acc = fmaf(w[r][c].y, rt, acc);
                acc = fmaf(w[r][c].z, up, acc);
                acc = fmaf(w[r][c].w, dn, acc);
                n[r][c] = acc;
            }
        }
#pragma unroll
        for (int r = 0; r < 3; r++)
#pragma unroll
            for (int c = 0; c < 3; c++) q[r][c] = n[r][c];

        if (it != KF - 1) {
            // publish only the 8 border cells of the patch
            qd[base]              = q[0][0];
            qd[base + 1]          = q[0][1];
            qd[base + 2]          = q[0][2];
            qd[base + RW]         = q[1][0];
            qd[base + RW + 2]     = q[1][2];
            qd[base + 2 * RW]     = q[2][0];
            qd[base + 2 * RW + 1] = q[2][1];
            qd[base + 2 * RW + 2] = q[2][2];
            __syncthreads();
        }
    }

    // ---- write central 32x32 from registers ----
#pragma unroll
    for (int r = 0; r < 3; r++) {
#pragma unroll
        for (int c = 0; c < 3; c++) {
            const int ly = py + r, lx = px + c;
            if (lx >= KF && lx < KF + TS && ly >= KF && ly < KF + TS) {
                const int gy = oy + ly, gx = ox + lx;
                const int g = gy * COLS + gx;
                if (FINAL) {
                    const float cd = conduit[g];
                    const float c125 = cd * sqrtf(sqrtf(cd));   // conduit^1.25
                    const float t = q[r][c] * FLOW_COEFF * c125;
                    const bool core = (gx >= 1) & (gx <= COLS - 2) & (gy >= 1) & (gy <= ROWS - 2);
                    out[g] = core ? (t * t) : 0.0f;
                } else {
                    qdst[g] = q[r][c];
                }
            }
        }
    }
}

extern "C" void kernel_launch(void* const* d_in, const int* in_sizes, int n_in,
                              void* d_out, int out_size) {
    const float* melt    = (const float*)d_in[0];
    const float* bed     = (const float*)d_in[1];
    const float* wp      = (const float*)d_in[2];
    const float* area    = (const float*)d_in[3];
    const float* conduit = (const float*)d_in[4];
    float* out = (float*)d_out;

    k_prep<<<NN / (256 * 4), 256>>>(melt, bed, wp, area);

    dim3 grid(COLS / TS, ROWS / TS);   // 32 x 32 tiles
    // 4 launches x 8 fused iterations = 32 iterations total
    k_fused<true,  false><<<grid, 256>>>(0, conduit, out);  // runoff -> g_q[1]
    k_fused<false, false><<<grid, 256>>>(1, conduit, out);  // g_q[1] -> g_q[0]
    k_fused<false, false><<<grid, 256>>>(0, conduit, out);  // g_q[0] -> g_q[1]
    k_fused<false, true ><<<grid, 256>>>(1, conduit, out);  // g_q[1] -> out
}

// round 7
// speedup vs baseline: 1.6895x; 1.6895x over previous
#include <cuda_runtime.h>

#define ROWS 1024
#define COLS 1024
#define NN (ROWS * COLS)

#define RHOGW 9810.0f            // RHO_W * GRAV
#define INV_SEC_PER_A (1.0f / 31556926.0f)
#define FLOW_COEFF 0.0405f

#define TS 32                    // output tile
#define KF 8                     // fused iterations per launch
#define RW (TS + 2*KF)           // 48
#define BP 49                    // compacted buffer pitch (conflict-free)
#define BR 34                    // compacted rows: 32 exchange rows + 2 guards

// Scratch (device globals: no allocations allowed)
__device__ float4 g_w4[NN];      // incoming weights: {left, right, up, down}
__device__ float  g_runoff[NN];
__device__ float  g_q[2][NN];

// ---------------- fused prep: phi -> gs -> w4 + runoff, one pass ----------------
#define PT 32
#define PH2 36
#define PH1 34

__global__ __launch_bounds__(256) void k_prep(const float* __restrict__ melt,
                                              const float* __restrict__ bed,
                                              const float* __restrict__ wp,
                                              const float* __restrict__ area,
                                              const int*  __restrict__ status) {
    __shared__ float sphi[PH2 * PH2];
    __shared__ float sgs[PH1 * PH1];
    const int ox = blockIdx.x * PT, oy = blockIdx.y * PT;

    for (int idx = threadIdx.x; idx < PH2 * PH2; idx += 256) {
        int iy = idx / PH2, ix = idx % PH2;
        int gy = oy + iy - 2, gx = ox + ix - 2;
        float p = __int_as_float(0x7f800000);     // +INF sentinel: contributes 0 drop
        if (gx >= 0 && gx < COLS && gy >= 0 && gy < ROWS) {
            int g = gy * COLS + gx;
            p = fmaf(RHOGW, bed[g], wp[g]);
        }
        sphi[idx] = p;
    }
    __syncthreads();

    for (int idx = threadIdx.x; idx < PH1 * PH1; idx += 256) {
        int iy = idx / PH1, ix = idx % PH1;
        int gy = oy + iy - 1, gx = ox + ix - 1;
        float gs = 0.0f;
        if (gx >= 0 && gx < COLS && gy >= 0 && gy < ROWS) {
            int g = gy * COLS + gx;
            if (status[g] == 0) {
                int c = (iy + 1) * PH2 + (ix + 1);
                float p = sphi[c];
                float s = 0.0f;
                s += fmaxf(p - sphi[c - 1], 0.0f);
                s += fmaxf(p - sphi[c + 1], 0.0f);
                s += fmaxf(p - sphi[c - PH2], 0.0f);
                s += fmaxf(p - sphi[c + PH2], 0.0f);
                gs = (s > 0.0f) ? (1.0f / s) : 1.0f;
            }
        }
        sgs[idx] = gs;
    }
    __syncthreads();

    for (int idx = threadIdx.x; idx < PT * PT; idx += 256) {
        int iy = idx / PT, ix = idx % PT;
        int gy = oy + iy, gx = ox + ix;
        int g = gy * COLS + gx;
        int cp = (iy + 2) * PH2 + (ix + 2);
        int cg = (iy + 1) * PH1 + (ix + 1);
        float p = sphi[cp];
        float4 w = make_float4(0.0f, 0.0f, 0.0f, 0.0f);
        if (gx > 0)        w.x = fmaxf(sphi[cp - 1]   - p, 0.0f) * sgs[cg - 1];
        if (gx < COLS - 1) w.y = fmaxf(sphi[cp + 1]   - p, 0.0f) * sgs[cg + 1];
        if (gy > 0)        w.z = fmaxf(sphi[cp - PH2] - p, 0.0f) * sgs[cg - PH1];
        if (gy < ROWS - 1) w.w = fmaxf(sphi[cp + PH2] - p, 0.0f) * sgs[cg + PH1];
        g_w4[g] = w;
        g_runoff[g] = melt[g] * area[g] * INV_SEC_PER_A;
    }
}

// ---------------- fused Jacobi: 8 iters, shuffle horizontal / smem vertical ----------------
// 256 threads (16x16), each owns a 3x3 patch of a 48x48 region (32x32 tile,
// halo 8). Weights/runoff/q in registers. Horizontal ring via warp shuffles
// (lane +/-1 within half-warp rows; edge lanes get contaminated-but-finite
// values, safe by the halo-margin argument). Vertical ring via a compacted
// smem buffer holding only patch rows 0 and 2 (34 rows x pitch 49).
template <bool INIT, bool FINAL>
__global__ __launch_bounds__(256, 3)
void k_fused(int qsel,
             const float* __restrict__ conduit,
             const int*  __restrict__ status,
             float* __restrict__ out) {
    __shared__ float sb[2][BR * BP];

    const int tid = threadIdx.x;
    const int tx = tid & 15, ty = tid >> 4;
    const int px = tx * 3, py = ty * 3;
    const int ox = blockIdx.x * TS - KF;
    const int oy = blockIdx.y * TS - KF;

    const float* __restrict__ qsrc = g_q[qsel];
    float*       __restrict__ qdst = g_q[qsel ^ 1];

    // compacted slots: guard 0, then (row0, row2) per ty, guard 33
    const int slotT = 2 * ty;          // region row py-1 (slot 0 = guard for ty==0)
    const int slot0 = 2 * ty + 1;      // own row 0
    const int slot2 = 2 * ty + 2;      // own row 2
    const int slotB = 2 * ty + 3;      // region row py+3 (slot 33 = guard for ty==15)

    // zero guard rows (both buffers, never written afterwards)
    if (tid < BP) {
        sb[0][tid] = 0.0f;
        sb[1][tid] = 0.0f;
        sb[0][(BR - 1) * BP + tid] = 0.0f;
        sb[1][(BR - 1) * BP + tid] = 0.0f;
    }

    float4 w[3][3];
    float  ro[3][3];
    float  q[3][3];
#pragma unroll
    for (int r = 0; r < 3; r++) {
#pragma unroll
        for (int c = 0; c < 3; c++) {
            const int gy = oy + py + r, gx = ox + px + c;
            const bool ok = (gx >= 0) & (gx < COLS) & (gy >= 0) & (gy < ROWS);
            const int g = gy * COLS + gx;
            float4 wv = make_float4(0.0f, 0.0f, 0.0f, 0.0f);
            float rv = 0.0f, qv = 0.0f;
            if (ok) {
                wv = g_w4[g];
                rv = g_runoff[g];
                qv = INIT ? rv : qsrc[g];
            }
            w[r][c] = wv; ro[r][c] = rv; q[r][c] = qv;
        }
    }
    // seed vertical-exchange rows (iteration-0 values)
#pragma unroll
    for (int c = 0; c < 3; c++) {
        sb[0][slot0 * BP + px + c] = q[0][c];
        sb[0][slot2 * BP + px + c] = q[2][c];
    }
    __syncthreads();

#pragma unroll
    for (int it = 0; it < KF; it++) {
        const int cur = it & 1;
        const float* __restrict__ qs = sb[cur];
        float*       __restrict__ qd = sb[cur ^ 1];

        // vertical ring (previous-iteration values from smem)
        const float t0 = qs[slotT * BP + px],     t1 = qs[slotT * BP + px + 1], t2 = qs[slotT * BP + px + 2];
        const float b0 = qs[slotB * BP + px],     b1 = qs[slotB * BP + px + 1], b2 = qs[slotB * BP + px + 2];
        // horizontal ring via shuffles of previous-iteration registers
        const float l0 = __shfl_up_sync(0xffffffffu, q[0][2], 1);
        const float l1 = __shfl_up_sync(0xffffffffu, q[1][2], 1);
        const float l2 = __shfl_up_sync(0xffffffffu, q[2][2], 1);
        const float r0 = __shfl_down_sync(0xffffffffu, q[0][0], 1);
        const float r1 = __shfl_down_sync(0xffffffffu, q[1][0], 1);
        const float r2 = __shfl_down_sync(0xffffffffu, q[2][0], 1);

        float n[3][3];
#pragma unroll
        for (int r = 0; r < 3; r++) {
#pragma unroll
            for (int c = 0; c < 3; c++) {
                const float lf = (c == 0) ? ((r == 0) ? l0 : (r == 1) ? l1 : l2) : q[r][c - 1];
                const float rt = (c == 2) ? ((r == 0) ? r0 : (r == 1) ? r1 : r2) : q[r][c + 1];
                const float up = (r == 0) ? ((c == 0) ? t0 : (c == 1) ? t1 : t2) : q[r - 1][c];
                const float dn = (r == 2) ? ((c == 0) ? b0 : (c == 1) ? b1 : b2) : q[r + 1][c];
                float acc = ro[r][c];
                acc = fmaf(w[r][c].x, lf, acc);
                acc = fmaf(w[r][c].y, rt, acc);
                acc = fmaf(w[r][c].z, up, acc);
                acc = fmaf(w[r][c].w, dn, acc);
                n[r][c] = acc;
            }
        }
#pragma unroll
        for (int r = 0; r < 3; r++)
#pragma unroll
            for (int c = 0; c < 3; c++) q[r][c] = n[r][c];

        if (it != KF - 1) {
            // publish only rows 0 and 2 (vertical exchange)
#pragma unroll
            for (int c = 0; c < 3; c++) {
                qd[slot0 * BP + px + c] = q[0][c];
                qd[slot2 * BP + px + c] = q[2][c];
            }
            __syncthreads();
        }
    }

    // write central 32x32 from registers
#pragma unroll
    for (int r = 0; r < 3; r++) {
#pragma unroll
        for (int c = 0; c < 3; c++) {
            const int ly = py + r, lx = px + c;
            if (lx >= KF && lx < KF + TS && ly >= KF && ly < KF + TS) {
                const int g = (oy + ly) * COLS + (ox + lx);
                if (FINAL) {
                    const float cd = conduit[g];
                    const float c125 = cd * sqrtf(sqrtf(cd));   // conduit^1.25
                    const float t = q[r][c] * FLOW_COEFF * c125;
                    out[g] = (status[g] == 0) ? (t * t) : 0.0f;
                } else {
                    qdst[g] = q[r][c];
                }
            }
        }
    }
}

extern "C" void kernel_launch(void* const* d_in, const int* in_sizes, int n_in,
                              void* d_out, int out_size) {
    const float* melt    = (const float*)d_in[0];
    const float* bed     = (const float*)d_in[1];
    const float* wp      = (const float*)d_in[2];
    const float* area    = (const float*)d_in[3];
    const float* conduit = (const float*)d_in[4];
    const int*   status  = (const int*)d_in[5];
    float* out = (float*)d_out;

    dim3 pgrid(COLS / PT, ROWS / PT);
    k_prep<<<pgrid, 256>>>(melt, bed, wp, area, status);

    dim3 grid(COLS / TS, ROWS / TS);   // 32 x 32 tiles
    // 4 launches x 8 fused iterations = 32 iterations total
    k_fused<true,  false><<<grid, 256>>>(0, conduit, status, out);  // runoff -> g_q[1]
    k_fused<false, false><<<grid, 256>>>(1, conduit, status, out);  // g_q[1] -> g_q[0]
    k_fused<false, false><<<grid, 256>>>(0, conduit, status, out);  // g_q[0] -> g_q[1]
    k_fused<false, true ><<<grid, 256>>>(1, conduit, status, out);  // g_q[1] -> out
}